// round 1
// baseline (speedup 1.0000x reference)
#include <cuda_runtime.h>
#include <cuda_bf16.h>
#include <cstdint>

#define EPS   1e-5f
#define NB    8
#define NC    256
#define HW    16384
#define CHW   (NC * HW)

// ---------------- device scratch (no allocations allowed) ----------------
__device__ float g_sum  [NB * NC];
__device__ float g_sumsq[NB * NC];
__device__ float g_A    [NB * NC * NC];   // folded per-batch mixing matrix (2 MB)
__device__ float g_E    [NB * NC];        // folded per-(b,o) bias

// ---------------- f32x2 packed-FMA helpers ----------------
typedef unsigned long long ull;

__device__ __forceinline__ ull ffma2(ull a, ull b, ull c) {
    ull d;
    asm("fma.rn.f32x2 %0, %1, %2, %3;" : "=l"(d) : "l"(a), "l"(b), "l"(c));
    return d;
}
__device__ __forceinline__ ull dup2(float v) {
    unsigned u = __float_as_uint(v);
    return ((ull)u << 32) | (ull)u;
}
__device__ __forceinline__ float lo32(ull v) { return __uint_as_float((unsigned)v); }
__device__ __forceinline__ float hi32(ull v) { return __uint_as_float((unsigned)(v >> 32)); }

// ========================================================================
// Kernel 1: per-(b,c) sum and sum-of-squares over H*W
// ========================================================================
__global__ __launch_bounds__(256) void stats_kernel(const float* __restrict__ x) {
    int bc = blockIdx.x;                       // 0 .. NB*NC-1
    const float4* xv = (const float4*)(x + (size_t)bc * HW);
    float s = 0.f, q = 0.f;
    #pragma unroll
    for (int j = 0; j < 16; j++) {
        float4 v = xv[threadIdx.x + j * 256];
        s += v.x + v.y + v.z + v.w;
        q += v.x * v.x + v.y * v.y + v.z * v.z + v.w * v.w;
    }
    #pragma unroll
    for (int off = 16; off; off >>= 1) {
        s += __shfl_xor_sync(0xffffffffu, s, off);
        q += __shfl_xor_sync(0xffffffffu, q, off);
    }
    __shared__ float ss[8], sq[8];
    int w = threadIdx.x >> 5, l = threadIdx.x & 31;
    if (l == 0) { ss[w] = s; sq[w] = q; }
    __syncthreads();
    if (threadIdx.x == 0) {
        float S = 0.f, Q = 0.f;
        #pragma unroll
        for (int i = 0; i < 8; i++) { S += ss[i]; Q += sq[i]; }
        g_sum[bc] = S;
        g_sumsq[bc] = Q;
    }
}

// ========================================================================
// Kernel 2: fold IN/LN stats + gamma/beta + W into per-batch GEMM (A, E)
// one block per batch, thread o handles output channel o
// ========================================================================
__global__ __launch_bounds__(256) void prep_kernel(const float* __restrict__ params,
                                                   const float* __restrict__ W) {
    int b = blockIdx.x;
    int o = threadIdx.x;                       // also channel index in phase 1

    __shared__ float sm[NC], sr[NC];
    __shared__ float redS[8], redQ[8];
    __shared__ float sMR[2];

    float s = g_sum[b * NC + o];
    float q = g_sumsq[b * NC + o];
    float m   = s * (1.f / (float)HW);
    float var = q * (1.f / (float)HW) - m * m;
    sm[o] = m;
    sr[o] = rsqrtf(var + EPS);

    // reduce channel sums -> LayerNorm stats
    float rs = s, rq = q;
    #pragma unroll
    for (int off = 16; off; off >>= 1) {
        rs += __shfl_xor_sync(0xffffffffu, rs, off);
        rq += __shfl_xor_sync(0xffffffffu, rq, off);
    }
    int w = o >> 5, l = o & 31;
    if (l == 0) { redS[w] = rs; redQ[w] = rq; }
    __syncthreads();
    if (o == 0) {
        float S = 0.f, Q = 0.f;
        #pragma unroll
        for (int i = 0; i < 8; i++) { S += redS[i]; Q += redQ[i]; }
        float M = S * (1.f / (float)CHW);
        float V = Q * (1.f / (float)CHW) - M * M;
        sMR[0] = M;
        sMR[1] = rsqrtf(V + EPS);
    }
    __syncthreads();
    float M = sMR[0], R = sMR[1];

    float gamma = params[b * 2 * NC + o];
    float beta  = params[b * 2 * NC + NC + o];
    const float* Wrow = W + o * 2 * NC;        // [W1(256) | W2(256)]
    float* Arow = g_A + ((size_t)(b * NC + o)) * NC;

    float d = 0.f, w2s = 0.f;
    for (int i = 0; i < NC; i++) {
        float w1 = Wrow[i];
        float w2 = Wrow[NC + i];
        float ri = sr[i];
        Arow[i] = gamma * (w1 * ri + R * w2);
        d   += w1 * ri * sm[i];
        w2s += w2;
    }
    g_E[b * NC + o] = beta - gamma * (d + R * M * w2s);
}

// ========================================================================
// Kernel 3: batched GEMM  out[b] = A[b](256x256) @ x[b](256x16384) + E
// BM=128 (o), BN=128 (pixels), BK=16, 256 threads, 8x8 per thread via f32x2
// ========================================================================
#define BM 128
#define BN 128
#define BK 16

__global__ __launch_bounds__(256, 2) void gemm_kernel(const float* __restrict__ x,
                                                      float* __restrict__ out) {
    __shared__ __align__(16) ull   As2[BK * BM];   // [k][o], value duplicated in both halves (16 KB)
    __shared__ __align__(16) float Xs [BK * BN];   // [k][p] (8 KB)

    int tid = threadIdx.x;
    int tx  = tid & 15;          // pixel micro-tile: p = tx*8 .. tx*8+7
    int ty  = tid >> 4;          // o micro-tile:     o = ty*8 .. ty*8+7
    int oT  = blockIdx.x * BM;   // gridDim.x = 2  (adjacent blocks share the X tile -> L2 reuse)
    int pT  = blockIdx.y * BN;   // gridDim.y = 128
    int b   = blockIdx.z;        // gridDim.z = 8

    const float* Ab = g_A + ((size_t)(b * NC + oT)) * NC;
    const float* Xb = x + (size_t)b * NC * HW;

    ull acc[8][4];
    #pragma unroll
    for (int i = 0; i < 8; i++)
        #pragma unroll
        for (int j = 0; j < 4; j++) acc[i][j] = 0ull;

    for (int k0 = 0; k0 < NC; k0 += BK) {
        // ---- load A tile (128 o x 16 k), store duplicated ----
        #pragma unroll
        for (int t = tid; t < 512; t += 256) {
            int kq = t & 3;          // which float4 along k
            int o  = t >> 2;         // 0..127
            float4 v = *(const float4*)(Ab + o * NC + k0 + kq * 4);
            As2[(kq * 4 + 0) * BM + o] = dup2(v.x);
            As2[(kq * 4 + 1) * BM + o] = dup2(v.y);
            As2[(kq * 4 + 2) * BM + o] = dup2(v.z);
            As2[(kq * 4 + 3) * BM + o] = dup2(v.w);
        }
        // ---- load X tile (16 k x 128 p), coalesced ----
        #pragma unroll
        for (int t = tid; t < 512; t += 256) {
            int i = t >> 5;          // 0..15
            int j = t & 31;
            float4 v = *(const float4*)(Xb + (size_t)(k0 + i) * HW + pT + j * 4);
            *(float4*)(Xs + i * BN + j * 4) = v;
        }
        __syncthreads();

        #pragma unroll
        for (int k = 0; k < BK; k++) {
            ull a2[8], b2[4];
            const ulonglong2* ar = (const ulonglong2*)(As2 + k * BM + ty * 8);
            #pragma unroll
            for (int j = 0; j < 4; j++) { a2[2*j] = ar[j].x; a2[2*j+1] = ar[j].y; }
            const ulonglong2* xr = (const ulonglong2*)((const ull*)(Xs + k * BN) + tx * 4);
            #pragma unroll
            for (int j = 0; j < 2; j++) { b2[2*j] = xr[j].x; b2[2*j+1] = xr[j].y; }
            #pragma unroll
            for (int i = 0; i < 8; i++)
                #pragma unroll
                for (int j = 0; j < 4; j++)
                    acc[i][j] = ffma2(a2[i], b2[j], acc[i][j]);
        }
        __syncthreads();
    }

    // ---- epilogue: add folded bias, write 8x8 tile ----
    #pragma unroll
    for (int i = 0; i < 8; i++) {
        int o = oT + ty * 8 + i;
        float e = g_E[b * NC + o];
        float* orow = out + ((size_t)(b * NC + o)) * HW + pT + tx * 8;
        float4 v0, v1;
        v0.x = lo32(acc[i][0]) + e;  v0.y = hi32(acc[i][0]) + e;
        v0.z = lo32(acc[i][1]) + e;  v0.w = hi32(acc[i][1]) + e;
        v1.x = lo32(acc[i][2]) + e;  v1.y = hi32(acc[i][2]) + e;
        v1.z = lo32(acc[i][3]) + e;  v1.w = hi32(acc[i][3]) + e;
        *(float4*)(orow)     = v0;
        *(float4*)(orow + 4) = v1;
    }
}

// ========================================================================
extern "C" void kernel_launch(void* const* d_in, const int* in_sizes, int n_in,
                              void* d_out, int out_size) {
    const float* x      = (const float*)d_in[0];   // [8,256,128,128]
    const float* params = (const float*)d_in[1];   // [8,512]
    const float* W      = (const float*)d_in[2];   // [256,512]
    float* out          = (float*)d_out;           // [8,256,128,128]

    stats_kernel<<<NB * NC, 256>>>(x);
    prep_kernel<<<NB, 256>>>(params, W);
    dim3 grid(NC / BM, HW / BN, NB);               // (2, 128, 8)
    gemm_kernel<<<grid, 256>>>(x, out);
}

// round 4
// speedup vs baseline: 1.4323x; 1.4323x over previous
#include <cuda_runtime.h>
#include <cuda_bf16.h>
#include <cstdint>

#define EPS   1e-5f
#define NB    8
#define NC    256
#define HW    16384
#define CHW   (NC * HW)

typedef unsigned int       u32;
typedef unsigned long long u64;
typedef unsigned short     u16;

// ---------------- device scratch (allocation-free) ----------------
__device__ float         g_sum  [NB * NC];
__device__ float         g_sumsq[NB * NC];
__device__ __nv_bfloat16 g_Ah[NB * NC * NC];   // folded matrix, bf16 hi (1 MB)
__device__ __nv_bfloat16 g_Al[NB * NC * NC];   // folded matrix, bf16 lo (1 MB)
__device__ float         g_E [NB * NC];

// ---------------- helpers ----------------
__device__ __forceinline__ u32 smem_u32(const void* p) {
    u32 a;
    asm("{ .reg .u64 t; cvta.to.shared.u64 t, %1; cvt.u32.u64 %0, t; }" : "=r"(a) : "l"(p));
    return a;
}
__device__ __forceinline__ void split_bf16(float f, u16& h, u16& l) {
    __nv_bfloat16 hb = __float2bfloat16(f);
    float fh = __bfloat162float(hb);
    __nv_bfloat16 lb = __float2bfloat16(f - fh);
    h = *(u16*)&hb;
    l = *(u16*)&lb;
}

#define LDMX4(r, addr) \
    asm volatile("ldmatrix.sync.aligned.m8n8.x4.shared.b16 {%0,%1,%2,%3}, [%4];" \
        : "=r"((r)[0]), "=r"((r)[1]), "=r"((r)[2]), "=r"((r)[3]) : "r"(addr))
#define LDMX4T(r, addr) \
    asm volatile("ldmatrix.sync.aligned.m8n8.x4.trans.shared.b16 {%0,%1,%2,%3}, [%4];" \
        : "=r"((r)[0]), "=r"((r)[1]), "=r"((r)[2]), "=r"((r)[3]) : "r"(addr))
#define MMA16816(c, a, b0, b1) \
    asm volatile("mma.sync.aligned.m16n8k16.row.col.f32.bf16.bf16.f32 " \
        "{%0,%1,%2,%3}, {%4,%5,%6,%7}, {%8,%9}, {%0,%1,%2,%3};" \
        : "+f"((c)[0]), "+f"((c)[1]), "+f"((c)[2]), "+f"((c)[3]) \
        : "r"((a)[0]), "r"((a)[1]), "r"((a)[2]), "r"((a)[3]), "r"(b0), "r"(b1))

// ========================================================================
// Kernel 1: per-(b,c) sum / sumsq over H*W   (measured 24.6us, 70% HBM)
// ========================================================================
__global__ __launch_bounds__(256) void stats_kernel(const float* __restrict__ x) {
    int bc = blockIdx.x;
    const float4* xv = (const float4*)(x + (size_t)bc * HW);
    float s = 0.f, q = 0.f;
    #pragma unroll
    for (int j = 0; j < 16; j++) {
        float4 v = xv[threadIdx.x + j * 256];
        s += v.x + v.y + v.z + v.w;
        q += v.x * v.x + v.y * v.y + v.z * v.z + v.w * v.w;
    }
    #pragma unroll
    for (int off = 16; off; off >>= 1) {
        s += __shfl_xor_sync(0xffffffffu, s, off);
        q += __shfl_xor_sync(0xffffffffu, q, off);
    }
    __shared__ float ss[8], sq[8];
    int w = threadIdx.x >> 5, l = threadIdx.x & 31;
    if (l == 0) { ss[w] = s; sq[w] = q; }
    __syncthreads();
    if (threadIdx.x == 0) {
        float S = 0.f, Q = 0.f;
        #pragma unroll
        for (int i = 0; i < 8; i++) { S += ss[i]; Q += sq[i]; }
        g_sum[bc] = S;
        g_sumsq[bc] = Q;
    }
}

// ========================================================================
// Kernel 2: fold stats + gamma/beta into Ah/Al (bf16 row-major) and E
// ========================================================================
__global__ __launch_bounds__(256) void prep_kernel(const float* __restrict__ params,
                                                   const float* __restrict__ W) {
    int b = blockIdx.x;
    int o = threadIdx.x;

    __shared__ float sm[NC], sr[NC];
    __shared__ float redS[8], redQ[8];
    __shared__ float sMR[2];

    float s = g_sum[b * NC + o];
    float q = g_sumsq[b * NC + o];
    float m   = s * (1.f / (float)HW);
    float var = q * (1.f / (float)HW) - m * m;
    sm[o] = m;
    sr[o] = rsqrtf(var + EPS);

    float rs = s, rq = q;
    #pragma unroll
    for (int off = 16; off; off >>= 1) {
        rs += __shfl_xor_sync(0xffffffffu, rs, off);
        rq += __shfl_xor_sync(0xffffffffu, rq, off);
    }
    int w = o >> 5, l = o & 31;
    if (l == 0) { redS[w] = rs; redQ[w] = rq; }
    __syncthreads();
    if (o == 0) {
        float S = 0.f, Q = 0.f;
        #pragma unroll
        for (int i = 0; i < 8; i++) { S += redS[i]; Q += redQ[i]; }
        float M = S * (1.f / (float)CHW);
        float V = Q * (1.f / (float)CHW) - M * M;
        sMR[0] = M;
        sMR[1] = rsqrtf(V + EPS);
    }
    __syncthreads();
    float M = sMR[0], R = sMR[1];

    float gamma = params[b * 2 * NC + o];
    float beta  = params[b * 2 * NC + NC + o];
    const float* Wrow = W + o * 2 * NC;
    __nv_bfloat16* ah = g_Ah + (size_t)(b * NC + o) * NC;
    __nv_bfloat16* al = g_Al + (size_t)(b * NC + o) * NC;

    float d = 0.f, w2s = 0.f;
    for (int i = 0; i < NC; i++) {
        float w1 = Wrow[i];
        float w2 = Wrow[NC + i];
        float ri = sr[i];
        float a  = gamma * (w1 * ri + R * w2);
        u16 h, lo;
        split_bf16(a, h, lo);
        ah[i] = *(__nv_bfloat16*)&h;
        al[i] = *(__nv_bfloat16*)&lo;
        d   += w1 * ri * sm[i];
        w2s += w2;
    }
    g_E[b * NC + o] = beta - gamma * (d + R * M * w2s);
}

// ========================================================================
// Kernel 3: HMMA GEMM  out[b][o][p] = sum_k A[b][o][k] x[b][k][p] + E
// CTA: 128(o) x 64(p), K chunks of 32. 256 threads = 8 warps (2M x 4N).
// Warp tile 64x16. bf16 hi/lo split, 3 products, fp32 accum.
// SMEM per buffer: Ah[128x32 pitch80B]=10240, Al=10240,
//                  Xh[32x64 pitch144B]=4608, Xl=4608  -> stride 30720, x2
// ========================================================================
#define BK      32
#define A_PITCH 80      // bytes (32 bf16 = 64B + 16B pad): conflict-free ldmatrix
#define X_PITCH 144     // bytes (64 bf16 = 128B + 16B pad)
#define BUF_STRIDE 30720

__global__ __launch_bounds__(256, 2) void gemm_kernel(const float* __restrict__ x,
                                                      float* __restrict__ out) {
    extern __shared__ __align__(16) char smem[];
    const u32 sb = smem_u32(smem);

    const int tid = threadIdx.x, lane = tid & 31, wid = tid >> 5;
    const int warp_m = wid >> 2;       // 0..1  -> 64 rows each
    const int warp_n = wid & 3;        // 0..3  -> 16 cols each
    const int oT = blockIdx.x * 128;   // gridDim.x = 2 (fastest: L2 reuse of x)
    const int pT = blockIdx.y * 64;    // gridDim.y = 256
    const int b  = blockIdx.z;

    const __nv_bfloat16* gAh = g_Ah + (size_t)(b * NC + oT) * NC;
    const __nv_bfloat16* gAl = g_Al + (size_t)(b * NC + oT) * NC;
    const float*         gX  = x + (size_t)b * NC * HW + pT;

    // ---- per-thread load assignments ----
    // A: 128 rows x 4 chunks(16B) = 512 units; units tid, tid+256
    const int ar0 = tid >> 2,        ac = tid & 3;
    const int ar1 = (tid + 256) >> 2;
    // X: 32 rows x 16 float4 = 512 units
    const int xk0 = tid >> 4,        xp = tid & 15;
    const int xk1 = (tid + 256) >> 4;

    uint4  pa0, pa1, pl0, pl1;
    float4 px0, px1;

    #define LOAD_CHUNK(kc) do { \
        pa0 = *(const uint4*)(gAh + (size_t)ar0 * NC + (kc) * BK + ac * 8); \
        pa1 = *(const uint4*)(gAh + (size_t)ar1 * NC + (kc) * BK + ac * 8); \
        pl0 = *(const uint4*)(gAl + (size_t)ar0 * NC + (kc) * BK + ac * 8); \
        pl1 = *(const uint4*)(gAl + (size_t)ar1 * NC + (kc) * BK + ac * 8); \
        px0 = *(const float4*)(gX + (size_t)((kc) * BK + xk0) * HW + xp * 4); \
        px1 = *(const float4*)(gX + (size_t)((kc) * BK + xk1) * HW + xp * 4); \
    } while (0)

    float acc[4][2][4];
    #pragma unroll
    for (int i = 0; i < 4; i++)
        #pragma unroll
        for (int j = 0; j < 2; j++)
            #pragma unroll
            for (int v = 0; v < 4; v++) acc[i][j][v] = 0.f;

    LOAD_CHUNK(0);

    for (int kc = 0; kc < NC / BK; kc++) {
        const u32 bufb = sb + (u32)(kc & 1) * BUF_STRIDE;
        const u32 AH = bufb, AL = bufb + 10240, XH = bufb + 20480, XL = bufb + 25088;

        // ---- stores into this buffer ----
        {
            u32 a0 = AH + (u32)ar0 * A_PITCH + (u32)ac * 16;
            u32 a1 = AH + (u32)ar1 * A_PITCH + (u32)ac * 16;
            asm volatile("st.shared.v4.b32 [%0], {%1,%2,%3,%4};" :: "r"(a0),
                         "r"(pa0.x), "r"(pa0.y), "r"(pa0.z), "r"(pa0.w) : "memory");
            asm volatile("st.shared.v4.b32 [%0], {%1,%2,%3,%4};" :: "r"(a1),
                         "r"(pa1.x), "r"(pa1.y), "r"(pa1.z), "r"(pa1.w) : "memory");
            u32 a2 = AL + (u32)ar0 * A_PITCH + (u32)ac * 16;
            u32 a3 = AL + (u32)ar1 * A_PITCH + (u32)ac * 16;
            asm volatile("st.shared.v4.b32 [%0], {%1,%2,%3,%4};" :: "r"(a2),
                         "r"(pl0.x), "r"(pl0.y), "r"(pl0.z), "r"(pl0.w) : "memory");
            asm volatile("st.shared.v4.b32 [%0], {%1,%2,%3,%4};" :: "r"(a3),
                         "r"(pl1.x), "r"(pl1.y), "r"(pl1.z), "r"(pl1.w) : "memory");

            const float4 pxs[2] = { px0, px1 };
            const int    xks[2] = { xk0, xk1 };
            #pragma unroll
            for (int u = 0; u < 2; u++) {
                u16 h[4], l[4];
                split_bf16(pxs[u].x, h[0], l[0]);
                split_bf16(pxs[u].y, h[1], l[1]);
                split_bf16(pxs[u].z, h[2], l[2]);
                split_bf16(pxs[u].w, h[3], l[3]);
                u32 h01 = (u32)h[0] | ((u32)h[1] << 16);
                u32 h23 = (u32)h[2] | ((u32)h[3] << 16);
                u32 l01 = (u32)l[0] | ((u32)l[1] << 16);
                u32 l23 = (u32)l[2] | ((u32)l[3] << 16);
                u32 xh = XH + (u32)xks[u] * X_PITCH + (u32)xp * 8;
                u32 xl = XL + (u32)xks[u] * X_PITCH + (u32)xp * 8;
                asm volatile("st.shared.v2.b32 [%0], {%1,%2};" :: "r"(xh), "r"(h01), "r"(h23) : "memory");
                asm volatile("st.shared.v2.b32 [%0], {%1,%2};" :: "r"(xl), "r"(l01), "r"(l23) : "memory");
            }
        }
        __syncthreads();

        if (kc < NC / BK - 1) LOAD_CHUNK(kc + 1);

        // ---- mma over this chunk (2 k16 steps) ----
        const u32 aBaseH = AH + (u32)(warp_m * 64 + (lane & 15)) * A_PITCH + (u32)(lane >> 4) * 16;
        const u32 aBaseL = AL + (u32)(warp_m * 64 + (lane & 15)) * A_PITCH + (u32)(lane >> 4) * 16;
        const u32 xBaseH = XH + (u32)(lane & 15) * X_PITCH + (u32)(lane >> 4) * 16 + (u32)warp_n * 32;
        const u32 xBaseL = XL + (u32)(lane & 15) * X_PITCH + (u32)(lane >> 4) * 16 + (u32)warp_n * 32;

        #pragma unroll
        for (int ks = 0; ks < 2; ks++) {
            u32 ah[4][4], al[4][4], bh[4], bl[4];
            #pragma unroll
            for (int mt = 0; mt < 4; mt++) {
                LDMX4(ah[mt], aBaseH + (u32)mt * (16 * A_PITCH) + (u32)ks * 32);
                LDMX4(al[mt], aBaseL + (u32)mt * (16 * A_PITCH) + (u32)ks * 32);
            }
            LDMX4T(bh, xBaseH + (u32)ks * (16 * X_PITCH));
            LDMX4T(bl, xBaseL + (u32)ks * (16 * X_PITCH));

            #pragma unroll
            for (int mt = 0; mt < 4; mt++) {
                #pragma unroll
                for (int nt = 0; nt < 2; nt++) {
                    MMA16816(acc[mt][nt], ah[mt], bh[nt * 2], bh[nt * 2 + 1]);
                    MMA16816(acc[mt][nt], ah[mt], bl[nt * 2], bl[nt * 2 + 1]);
                    MMA16816(acc[mt][nt], al[mt], bh[nt * 2], bh[nt * 2 + 1]);
                }
            }
        }
    }

    // ---- epilogue: add folded bias, write fp32 ----
    #pragma unroll
    for (int mt = 0; mt < 4; mt++) {
        int r = oT + warp_m * 64 + mt * 16 + (lane >> 2);
        float e0 = g_E[b * NC + r];
        float e1 = g_E[b * NC + r + 8];
        float* o0 = out + (size_t)(b * NC + r) * HW + pT + warp_n * 16 + (lane & 3) * 2;
        float* o1 = o0 + (size_t)8 * HW;
        #pragma unroll
        for (int nt = 0; nt < 2; nt++) {
            float2 v0 = { acc[mt][nt][0] + e0, acc[mt][nt][1] + e0 };
            float2 v1 = { acc[mt][nt][2] + e1, acc[mt][nt][3] + e1 };
            *(float2*)(o0 + nt * 8) = v0;
            *(float2*)(o1 + nt * 8) = v1;
        }
    }
}

// ========================================================================
extern "C" void kernel_launch(void* const* d_in, const int* in_sizes, int n_in,
                              void* d_out, int out_size) {
    const float* x      = (const float*)d_in[0];
    const float* params = (const float*)d_in[1];
    const float* W      = (const float*)d_in[2];
    float* out          = (float*)d_out;

    const int SMEM_BYTES = 2 * BUF_STRIDE;   // 60 KB
    cudaFuncSetAttribute(gemm_kernel, cudaFuncAttributeMaxDynamicSharedMemorySize, SMEM_BYTES);

    stats_kernel<<<NB * NC, 256>>>(x);
    prep_kernel<<<NB, 256>>>(params, W);
    dim3 grid(2, 256, NB);
    gemm_kernel<<<grid, 256, SMEM_BYTES>>>(x, out);
}